// round 2
// baseline (speedup 1.0000x reference)
#include <cuda_runtime.h>
#include <math.h>

// Problem constants
#define S_LEN 4096
#define HID   4096
#define NH    32
#define NKV   8
#define HD    128
#define NB    32          // S_LEN / 128
#define KVW   (NKV * HD)  // 1024

// Scratch (device globals: allocation-free contract)
__device__ float g_q[S_LEN * HID];       // 64 MB  [token][h*128+d] (rope'd)
__device__ float g_k[S_LEN * KVW];       // 16 MB  [token][kvh*128+d] (rope'd)
__device__ float g_v[S_LEN * KVW];       // 16 MB
__device__ float g_attn[S_LEN * HID];    // 64 MB  [token][h*128+d]
__device__ float g_cos[S_LEN * 64];
__device__ float g_sin[S_LEN * 64];

// ---------------------------------------------------------------------------
// RoPE tables in fp64 (tiny; runs once per graph replay)
// ---------------------------------------------------------------------------
__global__ void rope_table_kernel() {
    int idx = blockIdx.x * blockDim.x + threadIdx.x;
    if (idx >= S_LEN * 64) return;
    int j = idx & 63;
    int s = idx >> 6;
    double inv = pow(10000.0, -((double)(2 * j)) / 128.0);
    double a = (double)s * inv;
    g_cos[idx] = (float)cos(a);
    g_sin[idx] = (float)sin(a);
}

// x: [S_LEN, nh*128]; rotate halves (d, d+64) per head
__global__ void rope_apply_kernel(float* __restrict__ x, int nh) {
    int idx = blockIdx.x * blockDim.x + threadIdx.x;
    int total = S_LEN * nh * 64;
    if (idx >= total) return;
    int j = idx & 63;
    int h = (idx >> 6) % nh;
    int s = idx / (64 * nh);
    float c  = g_cos[s * 64 + j];
    float sn = g_sin[s * 64 + j];
    float* p = x + (size_t)s * nh * 128 + h * 128;
    float x1 = p[j];
    float x2 = p[j + 64];
    p[j]      = x1 * c - x2 * sn;
    p[j + 64] = x2 * c + x1 * sn;
}

// ---------------------------------------------------------------------------
// SGEMM: C[M,N] = A[M,K] @ B[K,N], all row-major, M,N mult of 128, K mult of 16
// 128x128 tile per CTA, 256 threads, 8x8 microtile. m <-> ty, n <-> tx.
// Double-buffered SMEM with register-staged prefetch: loads for tile t+1 are
// issued before computing tile t, hiding GMEM latency behind the FMA work.
// ---------------------------------------------------------------------------
__global__ __launch_bounds__(256) void sgemm128_kernel(
    const float* __restrict__ A, const float* __restrict__ B,
    float* __restrict__ C, int M, int N, int K)
{
    __shared__ float As[2][16][132];  // As[buf][k][m]
    __shared__ float Bs[2][16][132];  // Bs[buf][k][n]
    const int tid = threadIdx.x;
    const int tx = tid & 15;
    const int ty = tid >> 4;
    const int row0 = blockIdx.y * 128;
    const int col0 = blockIdx.x * 128;

    // Per-thread load indices (8 A elements, 8 B elements per tile)
    int am[8], ak[8], bk[8], bn[8];
    #pragma unroll
    for (int e = 0; e < 8; e++) {
        int t = tid + e * 256;
        am[e] = t >> 4;  ak[e] = t & 15;    // A tile 128x16
        bk[e] = t >> 7;  bn[e] = t & 127;   // B tile 16x128
    }

    float acc[8][8] = {{0.f}};
    const int ntiles = K >> 4;

    // Preload tile 0 into buffer 0
    #pragma unroll
    for (int e = 0; e < 8; e++) {
        As[0][ak[e]][am[e]] = A[(size_t)(row0 + am[e]) * K + ak[e]];
        Bs[0][bk[e]][bn[e]] = B[(size_t)bk[e] * N + (col0 + bn[e])];
    }
    __syncthreads();

    for (int t = 0; t < ntiles; t++) {
        const int buf = t & 1;
        float ra[8], rb[8];
        const bool more = (t + 1 < ntiles);
        if (more) {
            const int k0 = (t + 1) << 4;
            #pragma unroll
            for (int e = 0; e < 8; e++) {
                ra[e] = A[(size_t)(row0 + am[e]) * K + (k0 + ak[e])];
                rb[e] = B[(size_t)(k0 + bk[e]) * N + (col0 + bn[e])];
            }
        }

        #pragma unroll
        for (int kk = 0; kk < 16; kk++) {
            float a[8], b[8];
            *(float4*)&a[0] = *(const float4*)&As[buf][kk][ty * 8];
            *(float4*)&a[4] = *(const float4*)&As[buf][kk][ty * 8 + 4];
            *(float4*)&b[0] = *(const float4*)&Bs[buf][kk][tx * 8];
            *(float4*)&b[4] = *(const float4*)&Bs[buf][kk][tx * 8 + 4];
            #pragma unroll
            for (int i = 0; i < 8; i++)
                #pragma unroll
                for (int j = 0; j < 8; j++)
                    acc[i][j] += a[i] * b[j];
        }

        if (more) {
            const int nb_ = buf ^ 1;
            #pragma unroll
            for (int e = 0; e < 8; e++) {
                As[nb_][ak[e]][am[e]] = ra[e];
                Bs[nb_][bk[e]][bn[e]] = rb[e];
            }
            __syncthreads();
        }
    }

    #pragma unroll
    for (int i = 0; i < 8; i++) {
        float* cp = C + (size_t)(row0 + ty * 8 + i) * N + col0 + tx * 8;
        *(float4*)cp       = *(float4*)&acc[i][0];
        *(float4*)(cp + 4) = *(float4*)&acc[i][4];
    }
}

// ---------------------------------------------------------------------------
// Attention: one CTA per (q-block, head). Flash-style online softmax over
// K-blocks {0} U {max(1, qb-7) .. qb}. Causal mask only on diagonal block.
//   Qs: [d][qi]  stride 132    KVs: K as [d][r], V as [r][d], stride 132
//   Ss: [kj][qi] stride 132 (scores then probabilities)
// Microtile mapping: qi <-> tx (contiguous per thread), dj/kj <-> ty.
// ---------------------------------------------------------------------------
__global__ __launch_bounds__(256, 1) void attn_kernel(
    const float* __restrict__ Q, const float* __restrict__ K,
    const float* __restrict__ V, float* __restrict__ O)
{
    extern __shared__ float sm[];
    float* Qs   = sm;                   // 128*132
    float* KVs  = sm + 128 * 132;       // 128*132
    float* Ss   = sm + 2 * 128 * 132;   // 128*132
    float* corr = sm + 3 * 128 * 132;   // 128

    const int qb  = blockIdx.x;
    const int h   = blockIdx.y;
    const int kvh = h >> 2;             // GQA: 4 q-heads per kv-head
    const int tid = threadIdx.x;
    const int tx  = tid & 15;
    const int ty  = tid >> 4;
    const float scale = 0.08838834764831843f;  // 1/sqrt(128)

    // Load Q tile: Qs[d*132 + r] = Q[(qb*128+r)*HID + h*128 + d]
    for (int u = tid; u < 128 * 128; u += 256) {
        int d = u & 127, r = u >> 7;
        Qs[d * 132 + r] = Q[(size_t)(qb * 128 + r) * HID + h * 128 + d];
    }

    float m_r = -INFINITY;  // valid for tid < 128 (row owner)
    float l_r = 0.f;
    float acc[8][8] = {{0.f}};  // O[qi = tx*8+i][dj = ty*8+j]

    const int start = (qb - 7 > 1) ? (qb - 7) : 1;
    const int nkb = (qb >= 1) ? (qb - start + 2) : 1;

    for (int t = 0; t < nkb; t++) {
        const int kb = (t == 0) ? 0 : (start + t - 1);
        __syncthreads();  // KVs/Ss consumers from previous iter done

        // Load K block: KVs[d*132 + r]
        for (int u = tid; u < 128 * 128; u += 256) {
            int d = u & 127, r = u >> 7;
            KVs[d * 132 + r] = K[(size_t)(kb * 128 + r) * KVW + kvh * 128 + d];
        }
        __syncthreads();

        // S = Q . K^T  (s[i][j]: qi = tx*8+i, kj = ty*8+j)
        float s[8][8] = {{0.f}};
        #pragma unroll 4
        for (int d = 0; d < 128; d++) {
            float aq[8], ak[8];
            *(float4*)&aq[0] = *(const float4*)&Qs[d * 132 + tx * 8];
            *(float4*)&aq[4] = *(const float4*)&Qs[d * 132 + tx * 8 + 4];
            *(float4*)&ak[0] = *(const float4*)&KVs[d * 132 + ty * 8];
            *(float4*)&ak[4] = *(const float4*)&KVs[d * 132 + ty * 8 + 4];
            #pragma unroll
            for (int i = 0; i < 8; i++)
                #pragma unroll
                for (int j = 0; j < 8; j++)
                    s[i][j] += aq[i] * ak[j];
        }

        // Scale + mask, write S^T into Ss[kj][qi]
        const bool diag = (kb == qb);
        #pragma unroll
        for (int j = 0; j < 8; j++) {
            int kj = ty * 8 + j;
            float vals[8];
            #pragma unroll
            for (int i = 0; i < 8; i++) {
                float x = s[i][j] * scale;
                if (diag && kj > (tx * 8 + i)) x = -1e9f;
                vals[i] = x;
            }
            *(float4*)&Ss[kj * 132 + tx * 8]     = *(float4*)&vals[0];
            *(float4*)&Ss[kj * 132 + tx * 8 + 4] = *(float4*)&vals[4];
        }
        __syncthreads();

        // Online softmax: thread tid < 128 owns row qi = tid
        if (tid < 128) {
            const int row = tid;
            float mx = m_r;
            #pragma unroll 8
            for (int j = 0; j < 128; j++) mx = fmaxf(mx, Ss[j * 132 + row]);
            float cf = __expf(m_r - mx);
            float sum = 0.f;
            #pragma unroll 8
            for (int j = 0; j < 128; j++) {
                float p = __expf(Ss[j * 132 + row] - mx);
                Ss[j * 132 + row] = p;
                sum += p;
            }
            l_r = l_r * cf + sum;
            m_r = mx;
            corr[row] = cf;
        }
        __syncthreads();

        // Load V block (reuse KVs as [r][d]); rescale accumulators
        for (int u = tid; u < 128 * 128; u += 256) {
            int d = u & 127, r = u >> 7;
            KVs[r * 132 + d] = V[(size_t)(kb * 128 + r) * KVW + kvh * 128 + d];
        }
        #pragma unroll
        for (int i = 0; i < 8; i++) {
            float cf = corr[tx * 8 + i];
            #pragma unroll
            for (int j = 0; j < 8; j++) acc[i][j] *= cf;
        }
        __syncthreads();

        // O += P^T(Ss[k][qi]) . V(KVs[k][dj])
        #pragma unroll 4
        for (int k = 0; k < 128; k++) {
            float p[8], vv[8];
            *(float4*)&p[0]  = *(const float4*)&Ss[k * 132 + tx * 8];
            *(float4*)&p[4]  = *(const float4*)&Ss[k * 132 + tx * 8 + 4];
            *(float4*)&vv[0] = *(const float4*)&KVs[k * 132 + ty * 8];
            *(float4*)&vv[4] = *(const float4*)&KVs[k * 132 + ty * 8 + 4];
            #pragma unroll
            for (int i = 0; i < 8; i++)
                #pragma unroll
                for (int j = 0; j < 8; j++)
                    acc[i][j] += p[i] * vv[j];
        }
    }

    // Normalize and store: g_attn[(qb*128+qi)*HID + h*128 + dj]
    __syncthreads();
    if (tid < 128) corr[tid] = 1.0f / l_r;
    __syncthreads();
    #pragma unroll
    for (int i = 0; i < 8; i++) {
        float inv = corr[tx * 8 + i];
        float out[8];
        #pragma unroll
        for (int j = 0; j < 8; j++) out[j] = acc[i][j] * inv;
        float* op = O + (size_t)(qb * 128 + tx * 8 + i) * HID + h * 128 + ty * 8;
        *(float4*)op       = *(float4*)&out[0];
        *(float4*)(op + 4) = *(float4*)&out[4];
    }
}

// ---------------------------------------------------------------------------
// Launch
// ---------------------------------------------------------------------------
extern "C" void kernel_launch(void* const* d_in, const int* in_sizes, int n_in,
                              void* d_out, int out_size) {
    const float* hs = (const float*)d_in[0];
    const float* wq = (const float*)d_in[1];
    const float* wk = (const float*)d_in[2];
    const float* wv = (const float*)d_in[3];
    const float* wo = (const float*)d_in[4];
    float* out = (float*)d_out;

    float *pq, *pk, *pv, *pa;
    cudaGetSymbolAddress((void**)&pq, g_q);
    cudaGetSymbolAddress((void**)&pk, g_k);
    cudaGetSymbolAddress((void**)&pv, g_v);
    cudaGetSymbolAddress((void**)&pa, g_attn);

    const int ATTN_SMEM = (3 * 128 * 132 + 128) * (int)sizeof(float);  // 203264
    cudaFuncSetAttribute(attn_kernel,
                         cudaFuncAttributeMaxDynamicSharedMemorySize, ATTN_SMEM);

    // RoPE tables
    rope_table_kernel<<<(S_LEN * 64 + 255) / 256, 256>>>();

    // QKV projections
    sgemm128_kernel<<<dim3(HID / 128, S_LEN / 128), 256>>>(hs, wq, pq, S_LEN, HID, HID);
    sgemm128_kernel<<<dim3(KVW / 128, S_LEN / 128), 256>>>(hs, wk, pk, S_LEN, KVW, HID);
    sgemm128_kernel<<<dim3(KVW / 128, S_LEN / 128), 256>>>(hs, wv, pv, S_LEN, KVW, HID);

    // RoPE
    rope_apply_kernel<<<(S_LEN * NH * 64 + 255) / 256, 256>>>(pq, NH);
    rope_apply_kernel<<<(S_LEN * NKV * 64 + 255) / 256, 256>>>(pk, NKV);

    // Attention
    attn_kernel<<<dim3(NB, NH), 256, ATTN_SMEM>>>(pq, pk, pv, pa);

    // Output projection
    sgemm128_kernel<<<dim3(HID / 128, S_LEN / 128), 256>>>(pa, wo, out, S_LEN, HID, HID);
}

// round 4
// speedup vs baseline: 1.9035x; 1.9035x over previous
#include <cuda_runtime.h>
#include <cuda_bf16.h>
#include <math.h>
#include <stdint.h>

// Problem constants
#define S_LEN 4096
#define HID   4096
#define NH    32
#define NKV   8
#define HD    128
#define NB    32          // S_LEN / 128
#define KVW   (NKV * HD)  // 1024
#define MK    (S_LEN * HID)      // 16777216
#define MKV   (S_LEN * KVW)      // 4194304

// ---------------------------------------------------------------------------
// Scratch (device globals: allocation-free contract)
// ---------------------------------------------------------------------------
__device__ float g_q[MK];        // [token][h*128+d] (rope'd)
__device__ float g_k[MKV];
__device__ float g_v[MKV];
__device__ float g_attn[MK];     // [token][h*128+d]
__device__ float g_cos[S_LEN * 64];
__device__ float g_sin[S_LEN * 64];

// bf16 split-precision operands
__device__ __nv_bfloat16 g_hsh[MK],  g_hsl[MK];    // hidden_states hi/lo [M,K]
__device__ __nv_bfloat16 g_ath[MK],  g_atl[MK];    // attention out hi/lo [M,K]
__device__ __nv_bfloat16 g_wqth[MK], g_wqtl[MK];   // wq^T  [N=4096][K=4096]
__device__ __nv_bfloat16 g_wkth[MKV], g_wktl[MKV]; // wk^T  [N=1024][K=4096]
__device__ __nv_bfloat16 g_wvth[MKV], g_wvtl[MKV]; // wv^T
__device__ __nv_bfloat16 g_woth[MK], g_wotl[MK];   // wo^T  [N=4096][K=4096]

// ---------------------------------------------------------------------------
// PTX helpers (plain sm_100-legal: ldmatrix / mma.sync / cp.async only)
// ---------------------------------------------------------------------------
__device__ __forceinline__ uint32_t smem_to_u32(const void* p) {
    uint32_t a;
    asm("{ .reg .u64 t; cvta.to.shared.u64 t, %1; cvt.u32.u64 %0, t; }"
        : "=r"(a) : "l"(p));
    return a;
}

#define CP16(dst, src) \
    asm volatile("cp.async.cg.shared.global [%0], [%1], 16;" \
        :: "r"(dst), "l"(src))
#define CP_COMMIT() asm volatile("cp.async.commit_group;" ::: "memory")
#define CP_WAIT(n)  asm volatile("cp.async.wait_group %0;" :: "n"(n) : "memory")

__device__ __forceinline__ void ldsm4(uint32_t* r, uint32_t addr) {
    asm volatile("ldmatrix.sync.aligned.m8n8.x4.shared.b16 {%0,%1,%2,%3}, [%4];"
        : "=r"(r[0]), "=r"(r[1]), "=r"(r[2]), "=r"(r[3]) : "r"(addr));
}

__device__ __forceinline__ void mma16816(float* d, const uint32_t* a, const uint32_t* b) {
    asm volatile(
        "mma.sync.aligned.m16n8k16.row.col.f32.bf16.bf16.f32 "
        "{%0,%1,%2,%3}, {%4,%5,%6,%7}, {%8,%9}, {%0,%1,%2,%3};"
        : "+f"(d[0]), "+f"(d[1]), "+f"(d[2]), "+f"(d[3])
        : "r"(a[0]), "r"(a[1]), "r"(a[2]), "r"(a[3]), "r"(b[0]), "r"(b[1]));
}

// ---------------------------------------------------------------------------
// RoPE tables in fp64
// ---------------------------------------------------------------------------
__global__ void rope_table_kernel() {
    int idx = blockIdx.x * blockDim.x + threadIdx.x;
    if (idx >= S_LEN * 64) return;
    int j = idx & 63;
    int s = idx >> 6;
    double inv = pow(10000.0, -((double)(2 * j)) / 128.0);
    double a = (double)s * inv;
    g_cos[idx] = (float)cos(a);
    g_sin[idx] = (float)sin(a);
}

__global__ void rope_apply_kernel(float* __restrict__ x, int nh) {
    int idx = blockIdx.x * blockDim.x + threadIdx.x;
    int total = S_LEN * nh * 64;
    if (idx >= total) return;
    int j = idx & 63;
    int h = (idx >> 6) % nh;
    int s = idx / (64 * nh);
    float c  = g_cos[s * 64 + j];
    float sn = g_sin[s * 64 + j];
    float* p = x + (size_t)s * nh * 128 + h * 128;
    float x1 = p[j];
    float x2 = p[j + 64];
    p[j]      = x1 * c - x2 * sn;
    p[j + 64] = x2 * c + x1 * sn;
}

// ---------------------------------------------------------------------------
// fp32 -> bf16 (hi, lo) split, same layout
// ---------------------------------------------------------------------------
__global__ void split_rm_kernel(const float* __restrict__ X,
                                __nv_bfloat16* __restrict__ H,
                                __nv_bfloat16* __restrict__ L, int n4) {
    int i = blockIdx.x * blockDim.x + threadIdx.x;
    if (i >= n4) return;
    float4 v = *(const float4*)(X + (size_t)i * 4);
    const float* f = (const float*)&v;
    __nv_bfloat16 h[4], l[4];
    #pragma unroll
    for (int j = 0; j < 4; j++) {
        h[j] = __float2bfloat16_rn(f[j]);
        l[j] = __float2bfloat16_rn(f[j] - __bfloat162float(h[j]));
    }
    *(uint2*)(H + (size_t)i * 4) = *(uint2*)h;
    *(uint2*)(L + (size_t)i * 4) = *(uint2*)l;
}

// ---------------------------------------------------------------------------
// fp32 W[K,N] -> bf16 (hi, lo) transposed [N,K]
// ---------------------------------------------------------------------------
__global__ void split_tr_kernel(const float* __restrict__ W,
                                __nv_bfloat16* __restrict__ TH,
                                __nv_bfloat16* __restrict__ TL, int K, int N) {
    __shared__ float t[32][33];
    int k0 = blockIdx.y * 32, n0 = blockIdx.x * 32;
    int tx = threadIdx.x, ty = threadIdx.y;  // block (32, 8)
    #pragma unroll
    for (int i = 0; i < 32; i += 8)
        t[ty + i][tx] = W[(size_t)(k0 + ty + i) * N + n0 + tx];
    __syncthreads();
    #pragma unroll
    for (int i = 0; i < 32; i += 8) {
        float v = t[tx][ty + i];
        __nv_bfloat16 h = __float2bfloat16_rn(v);
        __nv_bfloat16 l = __float2bfloat16_rn(v - __bfloat162float(h));
        size_t o = (size_t)(n0 + ty + i) * K + k0 + tx;
        TH[o] = h;
        TL[o] = l;
    }
}

// ---------------------------------------------------------------------------
// mma.sync split-bf16 GEMM: C[M,N] = A[M,K] @ Bt[N,K]^T  (fp32-accurate)
// CTA: 128x128 C tile, 256 threads = 8 warps (2x4), warp tile 64x32.
// K consumed in 32-elem chunks, cp.async double-buffered SMEM.
// SMEM row stride 80B (40 bf16) -> conflict-free ldmatrix.
// Stage layout: Ah @0, Al @10240, Bh @20480, Bl @30720; stage size 40960.
// ---------------------------------------------------------------------------
#define STAGE_SZ 40960
#define GEMM_SMEM (2 * STAGE_SZ)

__global__ __launch_bounds__(256, 1) void gemm_bf16x3_kernel(
    const __nv_bfloat16* __restrict__ Ah, const __nv_bfloat16* __restrict__ Al,
    const __nv_bfloat16* __restrict__ Bh, const __nv_bfloat16* __restrict__ Bl,
    float* __restrict__ C, int N, int K)
{
    extern __shared__ char smem[];
    const uint32_t sb = smem_to_u32(smem);
    const int tid  = threadIdx.x;
    const int wid  = tid >> 5;
    const int lane = tid & 31;
    const int row0 = blockIdx.y * 128;
    const int col0 = blockIdx.x * 128;
    const int wm = (wid >> 2) * 64;   // warp M origin in tile
    const int wn = (wid & 3) * 32;    // warp N origin in tile

    // Per-thread cp.async geometry: 2 x 16B per array per chunk
    const int r0 = tid >> 2,          s0 = tid & 3;
    const int r1 = (tid + 256) >> 2,  s1 = tid & 3;  // idx+256 keeps seg: (tid+256)&3 == tid&3
    const long ga0 = (long)(row0 + r0) * K + s0 * 8;
    const long ga1 = (long)(row0 + r1) * K + s1 * 8;
    const long gb0 = (long)(col0 + r0) * K + s0 * 8;
    const long gb1 = (long)(col0 + r1) * K + s1 * 8;
    const uint32_t sd0 = (uint32_t)(r0 * 80 + s0 * 16);
    const uint32_t sd1 = (uint32_t)(r1 * 80 + s1 * 16);

    float d[4][4][4];
    #pragma unroll
    for (int i = 0; i < 4; i++)
        #pragma unroll
        for (int j = 0; j < 4; j++)
            #pragma unroll
            for (int q = 0; q < 4; q++) d[i][j][q] = 0.f;

    const int nch = K >> 5;

    // ldmatrix base addresses (per thread, relative to stage base)
    const uint32_t a_off = (uint32_t)((wm + (lane & 15)) * 80 + (lane >> 4) * 16);
    const uint32_t b_off = (uint32_t)((wn + (lane & 7) + (lane >> 4) * 8) * 80 +
                                      ((lane >> 3) & 1) * 16);

    // Prologue: chunk 0
    {
        const uint32_t st = sb;
        CP16(st +         sd0, Ah + ga0);  CP16(st +         sd1, Ah + ga1);
        CP16(st + 10240 + sd0, Al + ga0);  CP16(st + 10240 + sd1, Al + ga1);
        CP16(st + 20480 + sd0, Bh + gb0);  CP16(st + 20480 + sd1, Bh + gb1);
        CP16(st + 30720 + sd0, Bl + gb0);  CP16(st + 30720 + sd1, Bl + gb1);
        CP_COMMIT();
    }

    for (int c = 0; c < nch; c++) {
        if (c + 1 < nch) {
            const uint32_t st = sb + (uint32_t)((c + 1) & 1) * STAGE_SZ;
            const long o = (long)(c + 1) * 32;
            CP16(st +         sd0, Ah + ga0 + o);  CP16(st +         sd1, Ah + ga1 + o);
            CP16(st + 10240 + sd0, Al + ga0 + o);  CP16(st + 10240 + sd1, Al + ga1 + o);
            CP16(st + 20480 + sd0, Bh + gb0 + o);  CP16(st + 20480 + sd1, Bh + gb1 + o);
            CP16(st + 30720 + sd0, Bl + gb0 + o);  CP16(st + 30720 + sd1, Bl + gb1 + o);
            CP_COMMIT();
            CP_WAIT(1);
        } else {
            CP_WAIT(0);
        }
        __syncthreads();

        const uint32_t st = sb + (uint32_t)(c & 1) * STAGE_SZ;
        #pragma unroll
        for (int ks = 0; ks < 2; ks++) {
            uint32_t ah[4][4], al[4][4], bh[2][4], bl[2][4];
            const uint32_t kb = (uint32_t)(ks * 32);
            #pragma unroll
            for (int mi = 0; mi < 4; mi++) {
                uint32_t ad = st + a_off + (uint32_t)(mi * 16 * 80) + kb;
                ldsm4(ah[mi], ad);
                ldsm4(al[mi], ad + 10240);
            }
            #pragma unroll
            for (int pi = 0; pi < 2; pi++) {
                uint32_t bd = st + 20480 + b_off + (uint32_t)(pi * 16 * 80) + kb;
                ldsm4(bh[pi], bd);
                ldsm4(bl[pi], bd + 10240);
            }
            #pragma unroll
            for (int mi = 0; mi < 4; mi++)
                #pragma unroll
                for (int ni = 0; ni < 4; ni++) {
                    const uint32_t* bhp = &bh[ni >> 1][(ni & 1) * 2];
                    const uint32_t* blp = &bl[ni >> 1][(ni & 1) * 2];
                    mma16816(d[mi][ni], ah[mi], bhp);
                    mma16816(d[mi][ni], ah[mi], blp);
                    mma16816(d[mi][ni], al[mi], bhp);
                }
        }
        __syncthreads();
    }

    // Epilogue
    #pragma unroll
    for (int mi = 0; mi < 4; mi++)
        #pragma unroll
        for (int ni = 0; ni < 4; ni++) {
            int rr = row0 + wm + mi * 16 + (lane >> 2);
            int cc = col0 + wn + ni * 8 + (lane & 3) * 2;
            float2 v0 = make_float2(d[mi][ni][0], d[mi][ni][1]);
            float2 v1 = make_float2(d[mi][ni][2], d[mi][ni][3]);
            *(float2*)&C[(size_t)rr * N + cc]       = v0;
            *(float2*)&C[(size_t)(rr + 8) * N + cc] = v1;
        }
}

// ---------------------------------------------------------------------------
// Attention (fp32 SIMT, known-good): one CTA per (q-block, head).
// ---------------------------------------------------------------------------
__global__ __launch_bounds__(256, 1) void attn_kernel(
    const float* __restrict__ Q, const float* __restrict__ K,
    const float* __restrict__ V, float* __restrict__ O)
{
    extern __shared__ float sm[];
    float* Qs   = sm;                   // 128*132
    float* KVs  = sm + 128 * 132;       // 128*132
    float* Ss   = sm + 2 * 128 * 132;   // 128*132
    float* corr = sm + 3 * 128 * 132;   // 128

    const int qb  = blockIdx.x;
    const int h   = blockIdx.y;
    const int kvh = h >> 2;
    const int tid = threadIdx.x;
    const int tx  = tid & 15;
    const int ty  = tid >> 4;
    const float scale = 0.08838834764831843f;

    for (int u = tid; u < 128 * 128; u += 256) {
        int d = u & 127, r = u >> 7;
        Qs[d * 132 + r] = Q[(size_t)(qb * 128 + r) * HID + h * 128 + d];
    }

    float m_r = -INFINITY;
    float l_r = 0.f;
    float acc[8][8] = {{0.f}};

    const int start = (qb - 7 > 1) ? (qb - 7) : 1;
    const int nkb = (qb >= 1) ? (qb - start + 2) : 1;

    for (int t = 0; t < nkb; t++) {
        const int kb = (t == 0) ? 0 : (start + t - 1);
        __syncthreads();

        for (int u = tid; u < 128 * 128; u += 256) {
            int d = u & 127, r = u >> 7;
            KVs[d * 132 + r] = K[(size_t)(kb * 128 + r) * KVW + kvh * 128 + d];
        }
        __syncthreads();

        float s[8][8] = {{0.f}};
        #pragma unroll 4
        for (int d = 0; d < 128; d++) {
            float aq[8], ak[8];
            *(float4*)&aq[0] = *(const float4*)&Qs[d * 132 + tx * 8];
            *(float4*)&aq[4] = *(const float4*)&Qs[d * 132 + tx * 8 + 4];
            *(float4*)&ak[0] = *(const float4*)&KVs[d * 132 + ty * 8];
            *(float4*)&ak[4] = *(const float4*)&KVs[d * 132 + ty * 8 + 4];
            #pragma unroll
            for (int i = 0; i < 8; i++)
                #pragma unroll
                for (int j = 0; j < 8; j++)
                    s[i][j] += aq[i] * ak[j];
        }

        const bool diag = (kb == qb);
        #pragma unroll
        for (int j = 0; j < 8; j++) {
            int kj = ty * 8 + j;
            float vals[8];
            #pragma unroll
            for (int i = 0; i < 8; i++) {
                float x = s[i][j] * scale;
                if (diag && kj > (tx * 8 + i)) x = -1e9f;
                vals[i] = x;
            }
            *(float4*)&Ss[kj * 132 + tx * 8]     = *(float4*)&vals[0];
            *(float4*)&Ss[kj * 132 + tx * 8 + 4] = *(float4*)&vals[4];
        }
        __syncthreads();

        if (tid < 128) {
            const int row = tid;
            float mx = m_r;
            #pragma unroll 8
            for (int j = 0; j < 128; j++) mx = fmaxf(mx, Ss[j * 132 + row]);
            float cf = __expf(m_r - mx);
            float sum = 0.f;
            #pragma unroll 8
            for (int j = 0; j < 128; j++) {
                float p = __expf(Ss[j * 132 + row] - mx);
                Ss[j * 132 + row] = p;
                sum += p;
            }
            l_r = l_r * cf + sum;
            m_r = mx;
            corr[row] = cf;
        }
        __syncthreads();

        for (int u = tid; u < 128 * 128; u += 256) {
            int d = u & 127, r = u >> 7;
            KVs[r * 132 + d] = V[(size_t)(kb * 128 + r) * KVW + kvh * 128 + d];
        }
        #pragma unroll
        for (int i = 0; i < 8; i++) {
            float cf = corr[tx * 8 + i];
            #pragma unroll
            for (int j = 0; j < 8; j++) acc[i][j] *= cf;
        }
        __syncthreads();

        #pragma unroll 4
        for (int k = 0; k < 128; k++) {
            float p[8], vv[8];
            *(float4*)&p[0]  = *(const float4*)&Ss[k * 132 + tx * 8];
            *(float4*)&p[4]  = *(const float4*)&Ss[k * 132 + tx * 8 + 4];
            *(float4*)&vv[0] = *(const float4*)&KVs[k * 132 + ty * 8];
            *(float4*)&vv[4] = *(const float4*)&KVs[k * 132 + ty * 8 + 4];
            #pragma unroll
            for (int i = 0; i < 8; i++)
                #pragma unroll
                for (int j = 0; j < 8; j++)
                    acc[i][j] += p[i] * vv[j];
        }
    }

    __syncthreads();
    if (tid < 128) corr[tid] = 1.0f / l_r;
    __syncthreads();
    #pragma unroll
    for (int i = 0; i < 8; i++) {
        float inv = corr[tx * 8 + i];
        float out[8];
        #pragma unroll
        for (int j = 0; j < 8; j++) out[j] = acc[i][j] * inv;
        float* op = O + (size_t)(qb * 128 + tx * 8 + i) * HID + h * 128 + ty * 8;
        *(float4*)op       = *(float4*)&out[0];
        *(float4*)(op + 4) = *(float4*)&out[4];
    }
}

// ---------------------------------------------------------------------------
// Launch
// ---------------------------------------------------------------------------
extern "C" void kernel_launch(void* const* d_in, const int* in_sizes, int n_in,
                              void* d_out, int out_size) {
    const float* hs = (const float*)d_in[0];
    const float* wq = (const float*)d_in[1];
    const float* wk = (const float*)d_in[2];
    const float* wv = (const float*)d_in[3];
    const float* wo = (const float*)d_in[4];
    float* out = (float*)d_out;

    float *pq, *pk, *pv, *pa;
    cudaGetSymbolAddress((void**)&pq, g_q);
    cudaGetSymbolAddress((void**)&pk, g_k);
    cudaGetSymbolAddress((void**)&pv, g_v);
    cudaGetSymbolAddress((void**)&pa, g_attn);

    __nv_bfloat16 *hsh, *hsl, *ath, *atl;
    __nv_bfloat16 *wqth, *wqtl, *wkth, *wktl, *wvth, *wvtl, *woth, *wotl;
    cudaGetSymbolAddress((void**)&hsh,  g_hsh);
    cudaGetSymbolAddress((void**)&hsl,  g_hsl);
    cudaGetSymbolAddress((void**)&ath,  g_ath);
    cudaGetSymbolAddress((void**)&atl,  g_atl);
    cudaGetSymbolAddress((void**)&wqth, g_wqth);
    cudaGetSymbolAddress((void**)&wqtl, g_wqtl);
    cudaGetSymbolAddress((void**)&wkth, g_wkth);
    cudaGetSymbolAddress((void**)&wktl, g_wktl);
    cudaGetSymbolAddress((void**)&wvth, g_wvth);
    cudaGetSymbolAddress((void**)&wvtl, g_wvtl);
    cudaGetSymbolAddress((void**)&woth, g_woth);
    cudaGetSymbolAddress((void**)&wotl, g_wotl);

    const int ATTN_SMEM = (3 * 128 * 132 + 128) * (int)sizeof(float);
    cudaFuncSetAttribute(attn_kernel,
                         cudaFuncAttributeMaxDynamicSharedMemorySize, ATTN_SMEM);
    cudaFuncSetAttribute(gemm_bf16x3_kernel,
                         cudaFuncAttributeMaxDynamicSharedMemorySize, GEMM_SMEM);

    // RoPE tables
    rope_table_kernel<<<(S_LEN * 64 + 255) / 256, 256>>>();

    // Split hidden_states (row-major) and weights (transposed) to bf16 hi/lo
    split_rm_kernel<<<(MK / 4 + 255) / 256, 256>>>(hs, hsh, hsl, MK / 4);
    split_tr_kernel<<<dim3(HID / 32, HID / 32), dim3(32, 8)>>>(wq, wqth, wqtl, HID, HID);
    split_tr_kernel<<<dim3(KVW / 32, HID / 32), dim3(32, 8)>>>(wk, wkth, wktl, HID, KVW);
    split_tr_kernel<<<dim3(KVW / 32, HID / 32), dim3(32, 8)>>>(wv, wvth, wvtl, HID, KVW);
    split_tr_kernel<<<dim3(HID / 32, HID / 32), dim3(32, 8)>>>(wo, woth, wotl, HID, HID);

    // QKV projections (mma.sync bf16 x3)
    gemm_bf16x3_kernel<<<dim3(HID / 128, S_LEN / 128), 256, GEMM_SMEM>>>(
        hsh, hsl, wqth, wqtl, pq, HID, HID);
    gemm_bf16x3_kernel<<<dim3(KVW / 128, S_LEN / 128), 256, GEMM_SMEM>>>(
        hsh, hsl, wkth, wktl, pk, KVW, HID);
    gemm_bf16x3_kernel<<<dim3(KVW / 128, S_LEN / 128), 256, GEMM_SMEM>>>(
        hsh, hsl, wvth, wvtl, pv, KVW, HID);

    // RoPE
    rope_apply_kernel<<<(S_LEN * NH * 64 + 255) / 256, 256>>>(pq, NH);
    rope_apply_kernel<<<(S_LEN * NKV * 64 + 255) / 256, 256>>>(pk, NKV);

    // Attention
    attn_kernel<<<dim3(NB, NH), 256, ATTN_SMEM>>>(pq, pk, pv, pa);

    // Output projection
    split_rm_kernel<<<(MK / 4 + 255) / 256, 256>>>(pa, ath, atl, MK / 4);
    gemm_bf16x3_kernel<<<dim3(HID / 128, S_LEN / 128), 256, GEMM_SMEM>>>(
        ath, atl, woth, wotl, out, HID, HID);
}